// round 1
// baseline (speedup 1.0000x reference)
#include <cuda_runtime.h>
#include <math.h>

#define BATCH 16
#define DIM 1024
#define HALF 512
#define NHEADS 16
#define HD 64
#define NN 1024      // 32*32 spatial
#define KMAX 256     // dim/4
#define NPAIR 512    // dim/2

// ---- scratch (static device globals; no runtime allocation allowed) ----
__device__ float g_q[BATCH * DIM * NN];            // 64 MB  (post ELU+1)
__device__ float g_k[BATCH * DIM * NN];            // 64 MB  (post ELU+1)
__device__ float g_kvp[BATCH * NHEADS * 4 * HD * HD]; // 16 MB (kv partials, s^2 applied)
__device__ float g_km[BATCH * DIM];                // mean of k over n
__device__ float g_z[BATCH * NHEADS * NN];         // 1/(q.km + 1e-6)
__device__ float g_ct[NPAIR * NN];                 // cos table [pair][n]
__device__ float g_st[NPAIR * NN];                 // sin table [pair][n]

// ---------------------------------------------------------------------------
// RoPE tables: pair p in [0,512). p<256: angle = y*theta[p]; else x*theta[p-256]
// ---------------------------------------------------------------------------
__global__ void rope_tables_kernel() {
    int i = blockIdx.x * 256 + threadIdx.x;   // 0 .. 512*1024-1 (exact)
    int p = i >> 10;
    int n = i & 1023;
    int pk = p & (KMAX - 1);
    float theta = powf(10000.0f, -(float)pk / (float)KMAX);
    float pos = (p < KMAX) ? (float)(n >> 5) : (float)(n & 31);
    float ang = pos * theta;
    g_ct[i] = cosf(ang);
    g_st[i] = sinf(ang);
}

// ---------------------------------------------------------------------------
// K1: grouped 1x1 conv as GEMM. C[o][n] = sum_i W[o][i] * Xg[i][n] + b[o],
// then elu+1 (= v+1 if v>0 else exp(v)).  M=1024, K=512, N=1024, 32 GEMMs.
// 128x128 tile, BK=16, 256 threads, 8x8 per thread.
// ---------------------------------------------------------------------------
__global__ __launch_bounds__(256) void qk_gemm_kernel(
    const float* __restrict__ x, const float* __restrict__ w,
    const float* __restrict__ bias) {
    int g = blockIdx.z & 1;
    int b = blockIdx.z >> 1;
    const float* A = w + g * (DIM * HALF);                  // (1024, 512)
    const float* B = x + b * (DIM * NN) + g * (HALF * NN);  // (512, 1024)
    float* C = (g == 0 ? g_q : g_k) + b * (DIM * NN);
    const float* bb = bias + g * DIM;
    int m0 = blockIdx.y * 128, n0 = blockIdx.x * 128;

    __shared__ float As[16][132];   // transposed A tile, padded
    __shared__ float Bs[16][128];

    int tid = threadIdx.x;
    int ty = tid >> 4, tx = tid & 15;
    float acc[8][8];
#pragma unroll
    for (int i = 0; i < 8; i++)
#pragma unroll
        for (int j = 0; j < 8; j++) acc[i][j] = 0.0f;

    for (int kt = 0; kt < HALF; kt += 16) {
#pragma unroll
        for (int l = 0; l < 2; l++) {
            int li = tid + l * 256;        // 0..511
            int ar = li >> 2;              // 0..127
            int ac = (li & 3) << 2;        // 0,4,8,12
            float4 va = *(const float4*)(A + (m0 + ar) * HALF + kt + ac);
            As[ac + 0][ar] = va.x; As[ac + 1][ar] = va.y;
            As[ac + 2][ar] = va.z; As[ac + 3][ar] = va.w;
            int br = li >> 5;              // 0..15
            int bc = (li & 31) << 2;       // 0..124
            *(float4*)(&Bs[br][bc]) = *(const float4*)(B + (kt + br) * NN + n0 + bc);
        }
        __syncthreads();
#pragma unroll
        for (int k = 0; k < 16; k++) {
            float af[8], bf[8];
            *(float4*)(af)     = *(float4*)&As[k][ty * 8];
            *(float4*)(af + 4) = *(float4*)&As[k][ty * 8 + 4];
            *(float4*)(bf)     = *(float4*)&Bs[k][tx * 8];
            *(float4*)(bf + 4) = *(float4*)&Bs[k][tx * 8 + 4];
#pragma unroll
            for (int i = 0; i < 8; i++)
#pragma unroll
                for (int j = 0; j < 8; j++) acc[i][j] += af[i] * bf[j];
        }
        __syncthreads();
    }
#pragma unroll
    for (int i = 0; i < 8; i++) {
        int m = m0 + ty * 8 + i;
        float bv = bb[m];
#pragma unroll
        for (int j = 0; j < 8; j++) {
            float v = acc[i][j] + bv;
            acc[i][j] = (v > 0.0f) ? (v + 1.0f) : __expf(v);   // elu(v)+1
        }
        *(float4*)(C + m * NN + n0 + tx * 8)     = *(float4*)&acc[i][0];
        *(float4*)(C + m * NN + n0 + tx * 8 + 4) = *(float4*)&acc[i][4];
    }
}

// ---------------------------------------------------------------------------
// K2: km[b][c] = mean_n k[b][c][n]
// ---------------------------------------------------------------------------
__global__ void k_mean_kernel() {
    int bc = blockIdx.x;                         // 0..16383
    const float* kp = g_k + (size_t)bc * NN;
    int t = threadIdx.x;                         // 256
    float4 v = *(const float4*)(kp + t * 4);
    float s = v.x + v.y + v.z + v.w;
    __shared__ float red[8];
#pragma unroll
    for (int o = 16; o > 0; o >>= 1) s += __shfl_down_sync(0xffffffffu, s, o);
    if ((t & 31) == 0) red[t >> 5] = s;
    __syncthreads();
    if (t < 8) {
        s = red[t];
#pragma unroll
        for (int o = 4; o > 0; o >>= 1) s += __shfl_down_sync(0xffu, s, o);
        if (t == 0) g_km[bc] = s * (1.0f / NN);
    }
}

// ---------------------------------------------------------------------------
// K3: z[b][h][n] = 1 / (sum_d q[b][h*64+d][n] * km[b][h*64+d] + 1e-6)
// grid (4, NHEADS, BATCH), 256 threads
// ---------------------------------------------------------------------------
__global__ void z_kernel() {
    int b = blockIdx.z, h = blockIdx.y;
    int n = blockIdx.x * 256 + threadIdx.x;
    __shared__ float km[HD];
    if (threadIdx.x < HD) km[threadIdx.x] = g_km[b * DIM + h * HD + threadIdx.x];
    __syncthreads();
    const float* qp = g_q + (size_t)b * DIM * NN + h * HD * NN + n;
    float acc = 0.0f;
#pragma unroll 8
    for (int d = 0; d < HD; d++) acc += qp[d * NN] * km[d];
    g_z[(b * NHEADS + h) * NN + n] = 1.0f / (acc + 1e-6f);
}

// ---------------------------------------------------------------------------
// K4: kv partials. kvp[b][h][s][d][e] = s^2 * sum_{n in slice s} krope[d][n]*x[e][n]
// grid (4, NHEADS, BATCH), 256 threads, 4x4 per thread over 64x64 output
// ---------------------------------------------------------------------------
__global__ __launch_bounds__(256) void kv_kernel(const float* __restrict__ x) {
    int s = blockIdx.x, h = blockIdx.y, b = blockIdx.z;
    __shared__ float Ks[64][68];   // [n][d] roped k
    __shared__ float Vs[64][68];   // [n][e]
    int t = threadIdx.x;
    int ty = t >> 4, tx = t & 15;
    float acc[4][4];
#pragma unroll
    for (int i = 0; i < 4; i++)
#pragma unroll
        for (int j = 0; j < 4; j++) acc[i][j] = 0.0f;

    const float* kbase = g_k + (size_t)b * DIM * NN + h * HD * NN;
    const float* vbase = x + (size_t)b * DIM * NN + h * HD * NN;

    for (int sub = 0; sub < 4; sub++) {
        int nb = s * 256 + sub * 64;
        // rope-load K: 32 pairs x 64 n = 2048 pairs, 8 per thread
#pragma unroll
        for (int i = 0; i < 8; i++) {
            int pi = t + i * 256;
            int pd = pi >> 6;          // 0..31 pair-within-head
            int pn = pi & 63;
            int n = nb + pn;
            float k0 = kbase[(2 * pd) * NN + n];
            float k1 = kbase[(2 * pd + 1) * NN + n];
            int p = h * 32 + pd;
            float cs = g_ct[p * NN + n], sn = g_st[p * NN + n];
            Ks[pn][2 * pd]     = cs * k0 - sn * k1;
            Ks[pn][2 * pd + 1] = sn * k0 + cs * k1;
        }
        // V tile
#pragma unroll
        for (int i = 0; i < 16; i++) {
            int li = t + i * 256;
            int e = li >> 6, vn = li & 63;
            Vs[vn][e] = vbase[e * NN + nb + vn];
        }
        __syncthreads();
#pragma unroll
        for (int n = 0; n < 64; n++) {
            float a[4], v[4];
            *(float4*)a = *(float4*)&Ks[n][ty * 4];
            *(float4*)v = *(float4*)&Vs[n][tx * 4];
#pragma unroll
            for (int i = 0; i < 4; i++)
#pragma unroll
                for (int j = 0; j < 4; j++) acc[i][j] += a[i] * v[j];
        }
        __syncthreads();
    }
    const float s2 = 1.0f / 1024.0f;
    float* outp = g_kvp + (((size_t)(b * NHEADS + h) * 4 + s) * HD + ty * 4) * HD + tx * 4;
#pragma unroll
    for (int i = 0; i < 4; i++)
#pragma unroll
        for (int j = 0; j < 4; j++) outp[i * HD + j] = acc[i][j] * s2;
}

// ---------------------------------------------------------------------------
// K5: out[b][h*64+e][n] = z[n] * sum_d qrope[d][n]*kv[d][e]  + lepe(b, c, n)
// grid (16 ntiles, NHEADS, BATCH), 256 threads; thread = (nl = t/4, e0 = (t%4)*16)
// ---------------------------------------------------------------------------
__global__ __launch_bounds__(256) void out_kernel(
    const float* __restrict__ x, const float* __restrict__ lw,
    const float* __restrict__ lb, float* __restrict__ out) {
    int nt = blockIdx.x, h = blockIdx.y, b = blockIdx.z;
    __shared__ float KVs[64][68];   // [d][e]
    __shared__ float Qs[64][68];    // [n][d] roped q; reused as Os after compute
    int t = threadIdx.x;
    int nb = nt * 64;

    // sum the 4 kv partials
    const float* kvp = g_kvp + (size_t)(b * NHEADS + h) * 4 * 4096;
#pragma unroll
    for (int i = 0; i < 16; i++) {
        int li = t + i * 256;
        int d = li >> 6, e = li & 63;
        KVs[d][e] = kvp[li] + kvp[4096 + li] + kvp[8192 + li] + kvp[12288 + li];
    }
    // rope-load Q tile
    const float* qbase = g_q + (size_t)b * DIM * NN + h * HD * NN;
#pragma unroll
    for (int i = 0; i < 8; i++) {
        int pi = t + i * 256;
        int pd = pi >> 6, pn = pi & 63;
        int n = nb + pn;
        float q0 = qbase[(2 * pd) * NN + n];
        float q1 = qbase[(2 * pd + 1) * NN + n];
        int p = h * 32 + pd;
        float cs = g_ct[p * NN + n], sn = g_st[p * NN + n];
        Qs[pn][2 * pd]     = cs * q0 - sn * q1;
        Qs[pn][2 * pd + 1] = sn * q0 + cs * q1;
    }
    __syncthreads();

    int nl = t >> 2;
    int e0 = (t & 3) << 4;
    int n = nb + nl;
    float acc[16];
#pragma unroll
    for (int j = 0; j < 16; j++) acc[j] = 0.0f;
#pragma unroll
    for (int d = 0; d < 64; d++) {
        float qv = Qs[nl][d];
#pragma unroll
        for (int j = 0; j < 16; j += 4) {
            float4 kv4 = *(float4*)&KVs[d][e0 + j];
            acc[j + 0] += qv * kv4.x;
            acc[j + 1] += qv * kv4.y;
            acc[j + 2] += qv * kv4.z;
            acc[j + 3] += qv * kv4.w;
        }
    }
    float zv = g_z[(b * NHEADS + h) * NN + n];

    // fused lepe (depthwise 3x3, SAME) + bias, per channel
    int y = n >> 5, xx = n & 31;
    const float* xb = x + (size_t)b * DIM * NN;
    float res[16];
#pragma unroll
    for (int j = 0; j < 16; j++) {
        int c = h * HD + e0 + j;
        const float* xc = xb + c * NN;
        const float* wc = lw + c * 9;
        float lv = lb[c];
#pragma unroll
        for (int dy = -1; dy <= 1; dy++) {
            int yy = y + dy;
            if (yy < 0 || yy >= 32) continue;
#pragma unroll
            for (int dx = -1; dx <= 1; dx++) {
                int x2 = xx + dx;
                if (x2 < 0 || x2 >= 32) continue;
                lv += xc[yy * 32 + x2] * wc[(dy + 1) * 3 + (dx + 1)];
            }
        }
        res[j] = acc[j] * zv + lv;
    }

    // stage to smem (reuse Qs) and write coalesced
    __syncthreads();
    float* Os = &Qs[0][0];           // [e][nl] stride 65, 64*65 <= 64*68
#pragma unroll
    for (int j = 0; j < 16; j++) Os[(e0 + j) * 65 + nl] = res[j];
    __syncthreads();
    float* ob = out + (size_t)b * DIM * NN + h * HD * NN + nb;
#pragma unroll
    for (int i = 0; i < 16; i++) {
        int li = t + i * 256;
        int e = li >> 6, pn = li & 63;
        ob[e * NN + pn] = Os[e * 65 + pn];
    }
}

// ---------------------------------------------------------------------------
extern "C" void kernel_launch(void* const* d_in, const int* in_sizes, int n_in,
                              void* d_out, int out_size) {
    const float* x      = (const float*)d_in[0];
    const float* qk_w   = (const float*)d_in[1];
    const float* qk_b   = (const float*)d_in[2];
    const float* lepe_w = (const float*)d_in[3];
    const float* lepe_b = (const float*)d_in[4];
    float* out = (float*)d_out;

    rope_tables_kernel<<<(NPAIR * NN) / 256, 256>>>();
    qk_gemm_kernel<<<dim3(8, 8, BATCH * 2), 256>>>(x, qk_w, qk_b);
    k_mean_kernel<<<BATCH * DIM, 256>>>();
    z_kernel<<<dim3(4, NHEADS, BATCH), 256>>>();
    kv_kernel<<<dim3(4, NHEADS, BATCH), 256>>>(x);
    out_kernel<<<dim3(16, NHEADS, BATCH), 256>>>(x, lepe_w, lepe_b, out);
}

// round 2
// speedup vs baseline: 1.4858x; 1.4858x over previous
#include <cuda_runtime.h>
#include <cuda_bf16.h>
#include <math.h>

#define BATCH 16
#define DIM 1024
#define HALF 512
#define NHEADS 16
#define HD 64
#define NN 1024      // 32*32 spatial
#define KMAX 256     // dim/4
#define NPAIR 512    // dim/2

// ---- scratch (static device globals; no runtime allocation allowed) ----
__device__ float g_q[BATCH * DIM * NN];            // 64 MB  (post ELU+1)
__device__ float g_k[BATCH * DIM * NN];            // 64 MB  (post ELU+1)
__device__ float g_kvp[BATCH * NHEADS * 4 * HD * HD]; // 16 MB (kv partials)
__device__ float g_km[BATCH * DIM];
__device__ float g_z[BATCH * NHEADS * NN];
__device__ float g_ct[NPAIR * NN];
__device__ float g_st[NPAIR * NN];
// bf16 hi/lo split operands for the tensor-core GEMM
__device__ __nv_bfloat16 g_xhi[BATCH * DIM * NN];  // 32 MB
__device__ __nv_bfloat16 g_xlo[BATCH * DIM * NN];  // 32 MB
__device__ __nv_bfloat16 g_whi[2 * DIM * HALF];    // 2 MB
__device__ __nv_bfloat16 g_wlo[2 * DIM * HALF];    // 2 MB

// ---------------------------------------------------------------------------
// RoPE tables
// ---------------------------------------------------------------------------
__global__ void rope_tables_kernel() {
    int i = blockIdx.x * 256 + threadIdx.x;
    int p = i >> 10;
    int n = i & 1023;
    int pk = p & (KMAX - 1);
    float theta = powf(10000.0f, -(float)pk / (float)KMAX);
    float pos = (p < KMAX) ? (float)(n >> 5) : (float)(n & 31);
    float ang = pos * theta;
    g_ct[i] = cosf(ang);
    g_st[i] = sinf(ang);
}

// ---------------------------------------------------------------------------
// hi/lo bf16 split conversion
// ---------------------------------------------------------------------------
__global__ void convx_kernel(const float* __restrict__ x) {
    int i = (blockIdx.x * 256 + threadIdx.x) * 4;
    float4 v = *(const float4*)(x + i);
    __nv_bfloat16 h0 = __float2bfloat16(v.x), h1 = __float2bfloat16(v.y);
    __nv_bfloat16 h2 = __float2bfloat16(v.z), h3 = __float2bfloat16(v.w);
    __nv_bfloat162 p;
    p.x = h0; p.y = h1; *(__nv_bfloat162*)(g_xhi + i) = p;
    p.x = h2; p.y = h3; *(__nv_bfloat162*)(g_xhi + i + 2) = p;
    p.x = __float2bfloat16(v.x - __bfloat162float(h0));
    p.y = __float2bfloat16(v.y - __bfloat162float(h1));
    *(__nv_bfloat162*)(g_xlo + i) = p;
    p.x = __float2bfloat16(v.z - __bfloat162float(h2));
    p.y = __float2bfloat16(v.w - __bfloat162float(h3));
    *(__nv_bfloat162*)(g_xlo + i + 2) = p;
}

__global__ void convw_kernel(const float* __restrict__ w) {
    int i = (blockIdx.x * 256 + threadIdx.x) * 4;
    float4 v = *(const float4*)(w + i);
    __nv_bfloat16 h0 = __float2bfloat16(v.x), h1 = __float2bfloat16(v.y);
    __nv_bfloat16 h2 = __float2bfloat16(v.z), h3 = __float2bfloat16(v.w);
    __nv_bfloat162 p;
    p.x = h0; p.y = h1; *(__nv_bfloat162*)(g_whi + i) = p;
    p.x = h2; p.y = h3; *(__nv_bfloat162*)(g_whi + i + 2) = p;
    p.x = __float2bfloat16(v.x - __bfloat162float(h0));
    p.y = __float2bfloat16(v.y - __bfloat162float(h1));
    *(__nv_bfloat162*)(g_wlo + i) = p;
    p.x = __float2bfloat16(v.z - __bfloat162float(h2));
    p.y = __float2bfloat16(v.w - __bfloat162float(h3));
    *(__nv_bfloat162*)(g_wlo + i + 2) = p;
}

// ---------------------------------------------------------------------------
// K1 (tensor core): C = W@X per (batch, group), split bf16 3-pass,
// bias + elu + 1 fused. 128x128 tile, BK=32, 8 warps, mma.m16n8k16.
// ---------------------------------------------------------------------------
__device__ __forceinline__ void mma16816(float* c, const unsigned* a, const unsigned* b) {
    asm volatile(
        "mma.sync.aligned.m16n8k16.row.col.f32.bf16.bf16.f32 "
        "{%0,%1,%2,%3}, {%4,%5,%6,%7}, {%8,%9}, {%0,%1,%2,%3};\n"
        : "+f"(c[0]), "+f"(c[1]), "+f"(c[2]), "+f"(c[3])
        : "r"(a[0]), "r"(a[1]), "r"(a[2]), "r"(a[3]), "r"(b[0]), "r"(b[1]));
}
__device__ __forceinline__ void ldsm_x4(unsigned* r, unsigned addr) {
    asm volatile("ldmatrix.sync.aligned.m8n8.x4.shared.b16 {%0,%1,%2,%3}, [%4];\n"
                 : "=r"(r[0]), "=r"(r[1]), "=r"(r[2]), "=r"(r[3]) : "r"(addr));
}
__device__ __forceinline__ void ldsm_x2t(unsigned* r, unsigned addr) {
    asm volatile("ldmatrix.sync.aligned.m8n8.x2.trans.shared.b16 {%0,%1}, [%2];\n"
                 : "=r"(r[0]), "=r"(r[1]) : "r"(addr));
}
__device__ __forceinline__ unsigned smem_u32(const void* p) {
    return (unsigned)__cvta_generic_to_shared(p);
}

#define AST 40    // A smem row stride (bf16), 80B: 16B-aligned, conflict-free
#define BST 136   // B smem row stride (bf16), 272B

__global__ __launch_bounds__(256) void qk_gemm_tc(const float* __restrict__ bias) {
    int g = blockIdx.z & 1;
    int b = blockIdx.z >> 1;
    const __nv_bfloat16* Ahi = g_whi + g * (DIM * HALF);
    const __nv_bfloat16* Alo = g_wlo + g * (DIM * HALF);
    const __nv_bfloat16* Bhi = g_xhi + (size_t)b * (DIM * NN) + g * (HALF * NN);
    const __nv_bfloat16* Blo = g_xlo + (size_t)b * (DIM * NN) + g * (HALF * NN);
    float* C = (g == 0 ? g_q : g_k) + (size_t)b * DIM * NN;
    const float* bb = bias + g * DIM;
    int m0 = blockIdx.y * 128, n0 = blockIdx.x * 128;

    __shared__ __nv_bfloat16 As[2][128 * AST];   // [hi/lo][m][k]
    __shared__ __nv_bfloat16 Bs[2][32 * BST];    // [hi/lo][k][n]

    int t = threadIdx.x;
    int lane = t & 31;
    int warp = t >> 5;
    int wm = warp >> 2;          // 0..1 -> m offset *64
    int wn = warp & 3;           // 0..3 -> n offset *32

    float acc[4][4][4];
#pragma unroll
    for (int i = 0; i < 4; i++)
#pragma unroll
        for (int j = 0; j < 4; j++)
#pragma unroll
            for (int r = 0; r < 4; r++) acc[i][j][r] = 0.0f;

    // load index precompute
    int ar = t >> 2;             // 0..63 (A row, +64 second)
    int ac = (t & 3) * 8;        // A col chunk
    int bk = t >> 4;             // 0..15 (B row k, +16 second)
    int bc = (t & 15) * 8;       // B col chunk

    unsigned as_hi = smem_u32(&As[0][0]);
    unsigned as_lo = smem_u32(&As[1][0]);
    unsigned bs_hi = smem_u32(&Bs[0][0]);
    unsigned bs_lo = smem_u32(&Bs[1][0]);
    int lr = lane & 15, lh = lane >> 4;

    for (int kt = 0; kt < HALF; kt += 32) {
        // --- stage A (hi, lo): 128 x 32 each ---
        *(uint4*)(&As[0][ar * AST + ac]) = *(const uint4*)(Ahi + (m0 + ar) * HALF + kt + ac);
        *(uint4*)(&As[0][(ar + 64) * AST + ac]) = *(const uint4*)(Ahi + (m0 + ar + 64) * HALF + kt + ac);
        *(uint4*)(&As[1][ar * AST + ac]) = *(const uint4*)(Alo + (m0 + ar) * HALF + kt + ac);
        *(uint4*)(&As[1][(ar + 64) * AST + ac]) = *(const uint4*)(Alo + (m0 + ar + 64) * HALF + kt + ac);
        // --- stage B (hi, lo): 32 x 128 each ---
        *(uint4*)(&Bs[0][bk * BST + bc]) = *(const uint4*)(Bhi + (size_t)(kt + bk) * NN + n0 + bc);
        *(uint4*)(&Bs[0][(bk + 16) * BST + bc]) = *(const uint4*)(Bhi + (size_t)(kt + bk + 16) * NN + n0 + bc);
        *(uint4*)(&Bs[1][bk * BST + bc]) = *(const uint4*)(Blo + (size_t)(kt + bk) * NN + n0 + bc);
        *(uint4*)(&Bs[1][(bk + 16) * BST + bc]) = *(const uint4*)(Blo + (size_t)(kt + bk + 16) * NN + n0 + bc);
        __syncthreads();

#pragma unroll
        for (int k0 = 0; k0 < 32; k0 += 16) {
            unsigned ahi[4][4], alo[4][4], bhi[4][2], blo[4][2];
            unsigned aoff = ((wm * 64 + lr) * AST + k0 + lh * 8) * 2;
#pragma unroll
            for (int mi = 0; mi < 4; mi++) {
                ldsm_x4(ahi[mi], as_hi + aoff + mi * 16 * AST * 2);
                ldsm_x4(alo[mi], as_lo + aoff + mi * 16 * AST * 2);
            }
            unsigned boff = ((k0 + lr) * BST + wn * 32) * 2;
#pragma unroll
            for (int ni = 0; ni < 4; ni++) {
                ldsm_x2t(bhi[ni], bs_hi + boff + ni * 16);
                ldsm_x2t(blo[ni], bs_lo + boff + ni * 16);
            }
#pragma unroll
            for (int mi = 0; mi < 4; mi++)
#pragma unroll
                for (int ni = 0; ni < 4; ni++) {
                    mma16816(acc[mi][ni], ahi[mi], bhi[ni]);
                    mma16816(acc[mi][ni], ahi[mi], blo[ni]);
                    mma16816(acc[mi][ni], alo[mi], bhi[ni]);
                }
        }
        __syncthreads();
    }

    // epilogue: bias + elu + 1, store fp32
    int r0 = lane >> 2, c0 = 2 * (lane & 3);
#pragma unroll
    for (int mi = 0; mi < 4; mi++) {
        int mrow = m0 + wm * 64 + mi * 16 + r0;
        float b1 = bb[mrow], b2 = bb[mrow + 8];
#pragma unroll
        for (int ni = 0; ni < 4; ni++) {
            int ncol = n0 + wn * 32 + ni * 8 + c0;
            float* a = acc[mi][ni];
            float v;
            v = a[0] + b1; a[0] = (v > 0.0f) ? v + 1.0f : __expf(v);
            v = a[1] + b1; a[1] = (v > 0.0f) ? v + 1.0f : __expf(v);
            v = a[2] + b2; a[2] = (v > 0.0f) ? v + 1.0f : __expf(v);
            v = a[3] + b2; a[3] = (v > 0.0f) ? v + 1.0f : __expf(v);
            *(float2*)(C + (size_t)mrow * NN + ncol) = make_float2(a[0], a[1]);
            *(float2*)(C + (size_t)(mrow + 8) * NN + ncol) = make_float2(a[2], a[3]);
        }
    }
}

// ---------------------------------------------------------------------------
// K2: km[b][c] = mean_n k[b][c][n]
// ---------------------------------------------------------------------------
__global__ void k_mean_kernel() {
    int bc = blockIdx.x;
    const float* kp = g_k + (size_t)bc * NN;
    int t = threadIdx.x;
    float4 v = *(const float4*)(kp + t * 4);
    float s = v.x + v.y + v.z + v.w;
    __shared__ float red[8];
#pragma unroll
    for (int o = 16; o > 0; o >>= 1) s += __shfl_down_sync(0xffffffffu, s, o);
    if ((t & 31) == 0) red[t >> 5] = s;
    __syncthreads();
    if (t < 8) {
        s = red[t];
#pragma unroll
        for (int o = 4; o > 0; o >>= 1) s += __shfl_down_sync(0xffu, s, o);
        if (t == 0) g_km[bc] = s * (1.0f / NN);
    }
}

// ---------------------------------------------------------------------------
// K3: z = 1/(q . km + 1e-6)
// ---------------------------------------------------------------------------
__global__ void z_kernel() {
    int b = blockIdx.z, h = blockIdx.y;
    int n = blockIdx.x * 256 + threadIdx.x;
    __shared__ float km[HD];
    if (threadIdx.x < HD) km[threadIdx.x] = g_km[b * DIM + h * HD + threadIdx.x];
    __syncthreads();
    const float* qp = g_q + (size_t)b * DIM * NN + h * HD * NN + n;
    float acc = 0.0f;
#pragma unroll 8
    for (int d = 0; d < HD; d++) acc += qp[d * NN] * km[d];
    g_z[(b * NHEADS + h) * NN + n] = 1.0f / (acc + 1e-6f);
}

// ---------------------------------------------------------------------------
// K4: kv partials with rope applied to k on load
// ---------------------------------------------------------------------------
__global__ __launch_bounds__(256) void kv_kernel(const float* __restrict__ x) {
    int s = blockIdx.x, h = blockIdx.y, b = blockIdx.z;
    __shared__ float Ks[64][68];
    __shared__ float Vs[64][68];
    int t = threadIdx.x;
    int ty = t >> 4, tx = t & 15;
    float acc[4][4];
#pragma unroll
    for (int i = 0; i < 4; i++)
#pragma unroll
        for (int j = 0; j < 4; j++) acc[i][j] = 0.0f;

    const float* kbase = g_k + (size_t)b * DIM * NN + h * HD * NN;
    const float* vbase = x + (size_t)b * DIM * NN + h * HD * NN;

    for (int sub = 0; sub < 4; sub++) {
        int nb = s * 256 + sub * 64;
#pragma unroll
        for (int i = 0; i < 8; i++) {
            int pi = t + i * 256;
            int pd = pi >> 6;
            int pn = pi & 63;
            int n = nb + pn;
            float k0 = kbase[(2 * pd) * NN + n];
            float k1 = kbase[(2 * pd + 1) * NN + n];
            int p = h * 32 + pd;
            float cs = g_ct[p * NN + n], sn = g_st[p * NN + n];
            Ks[pn][2 * pd]     = cs * k0 - sn * k1;
            Ks[pn][2 * pd + 1] = sn * k0 + cs * k1;
        }
#pragma unroll
        for (int i = 0; i < 16; i++) {
            int li = t + i * 256;
            int e = li >> 6, vn = li & 63;
            Vs[vn][e] = vbase[e * NN + nb + vn];
        }
        __syncthreads();
#pragma unroll
        for (int n = 0; n < 64; n++) {
            float a[4], v[4];
            *(float4*)a = *(float4*)&Ks[n][ty * 4];
            *(float4*)v = *(float4*)&Vs[n][tx * 4];
#pragma unroll
            for (int i = 0; i < 4; i++)
#pragma unroll
                for (int j = 0; j < 4; j++) acc[i][j] += a[i] * v[j];
        }
        __syncthreads();
    }
    const float s2 = 1.0f / 1024.0f;
    float* outp = g_kvp + (((size_t)(b * NHEADS + h) * 4 + s) * HD + ty * 4) * HD + tx * 4;
#pragma unroll
    for (int i = 0; i < 4; i++)
#pragma unroll
        for (int j = 0; j < 4; j++) outp[i * HD + j] = acc[i][j] * s2;
}

// ---------------------------------------------------------------------------
// K5: out = z * (qrope @ kv) + lepe
// ---------------------------------------------------------------------------
__global__ __launch_bounds__(256) void out_kernel(
    const float* __restrict__ x, const float* __restrict__ lw,
    const float* __restrict__ lb, float* __restrict__ out) {
    int nt = blockIdx.x, h = blockIdx.y, b = blockIdx.z;
    __shared__ float KVs[64][68];
    __shared__ float Qs[64][68];
    int t = threadIdx.x;
    int nb = nt * 64;

    const float* kvp = g_kvp + (size_t)(b * NHEADS + h) * 4 * 4096;
#pragma unroll
    for (int i = 0; i < 16; i++) {
        int li = t + i * 256;
        int d = li >> 6, e = li & 63;
        KVs[d][e] = kvp[li] + kvp[4096 + li] + kvp[8192 + li] + kvp[12288 + li];
    }
    const float* qbase = g_q + (size_t)b * DIM * NN + h * HD * NN;
#pragma unroll
    for (int i = 0; i < 8; i++) {
        int pi = t + i * 256;
        int pd = pi >> 6, pn = pi & 63;
        int n = nb + pn;
        float q0 = qbase[(2 * pd) * NN + n];
        float q1 = qbase[(2 * pd + 1) * NN + n];
        int p = h * 32 + pd;
        float cs = g_ct[p * NN + n], sn = g_st[p * NN + n];
        Qs[pn][2 * pd]     = cs * q0 - sn * q1;
        Qs[pn][2 * pd + 1] = sn * q0 + cs * q1;
    }
    __syncthreads();

    int nl = t >> 2;
    int e0 = (t & 3) << 4;
    int n = nb + nl;
    float acc[16];
#pragma unroll
    for (int j = 0; j < 16; j++) acc[j] = 0.0f;
#pragma unroll
    for (int d = 0; d < 64; d++) {
        float qv = Qs[nl][d];
#pragma unroll
        for (int j = 0; j < 16; j += 4) {
            float4 kv4 = *(float4*)&KVs[d][e0 + j];
            acc[j + 0] += qv * kv4.x;
            acc[j + 1] += qv * kv4.y;
            acc[j + 2] += qv * kv4.z;
            acc[j + 3] += qv * kv4.w;
        }
    }
    float zv = g_z[(b * NHEADS + h) * NN + n];

    int y = n >> 5, xx = n & 31;
    const float* xb = x + (size_t)b * DIM * NN;
    float res[16];
#pragma unroll
    for (int j = 0; j < 16; j++) {
        int c = h * HD + e0 + j;
        const float* xc = xb + c * NN;
        const float* wc = lw + c * 9;
        float lv = lb[c];
#pragma unroll
        for (int dy = -1; dy <= 1; dy++) {
            int yy = y + dy;
            if (yy < 0 || yy >= 32) continue;
#pragma unroll
            for (int dx = -1; dx <= 1; dx++) {
                int x2 = xx + dx;
                if (x2 < 0 || x2 >= 32) continue;
                lv += xc[yy * 32 + x2] * wc[(dy + 1) * 3 + (dx + 1)];
            }
        }
        res[j] = acc[j] * zv + lv;
    }

    __syncthreads();
    float* Os = &Qs[0][0];
#pragma unroll
    for (int j = 0; j < 16; j++) Os[(e0 + j) * 65 + nl] = res[j];
    __syncthreads();
    float* ob = out + (size_t)b * DIM * NN + h * HD * NN + nb;
#pragma unroll
    for (int i = 0; i < 16; i++) {
        int li = t + i * 256;
        int e = li >> 6, pn = li & 63;
        ob[e * NN + pn] = Os[e * 65 + pn];
    }
}

// ---------------------------------------------------------------------------
extern "C" void kernel_launch(void* const* d_in, const int* in_sizes, int n_in,
                              void* d_out, int out_size) {
    const float* x      = (const float*)d_in[0];
    const float* qk_w   = (const float*)d_in[1];
    const float* qk_b   = (const float*)d_in[2];
    const float* lepe_w = (const float*)d_in[3];
    const float* lepe_b = (const float*)d_in[4];
    float* out = (float*)d_out;

    rope_tables_kernel<<<(NPAIR * NN) / 256, 256>>>();
    convw_kernel<<<(2 * DIM * HALF) / 1024, 256>>>(qk_w);
    convx_kernel<<<(BATCH * DIM * NN) / 1024, 256>>>(x);
    qk_gemm_tc<<<dim3(8, 8, BATCH * 2), 256>>>(qk_b);
    k_mean_kernel<<<BATCH * DIM, 256>>>();
    z_kernel<<<dim3(4, NHEADS, BATCH), 256>>>();
    kv_kernel<<<dim3(4, NHEADS, BATCH), 256>>>(x);
    out_kernel<<<dim3(16, NHEADS, BATCH), 256>>>(x, lepe_w, lepe_b, out);
}